// round 2
// baseline (speedup 1.0000x reference)
#include <cuda_runtime.h>
#include <math.h>
#include <stdint.h>

// ---------------- static problem sizes ----------------
#define NN  100000
#define EE  1600000
#define F0  512
#define D1  64
#define D2  256

// ---------------- device scratch (static, no runtime alloc) ----------------
__device__ float g_dinv[NN];
__device__ int   g_cnt[NN];
__device__ int   g_rowstart[NN + 1];
__device__ int   g_cursor[NN];
__device__ int   g_csr[EE];
__device__ float g_xw1[(size_t)NN * D1];   // x @ W1
__device__ float g_h1 [(size_t)NN * D1];   // relu(agg(xw1)+b1)
__device__ float g_a2 [(size_t)NN * D1];   // agg(h1)
__device__ float g_h2 [(size_t)NN * D2];   // relu(a2 @ W2 + b2)
__device__ float g_xw3[NN];                // h2 @ W3
__device__ float g_z  [NN];                // partial z (self term), then full z

// ---------------- init: zero counters + output ----------------
__global__ void init_kernel(float* out, int n) {
    int i = blockIdx.x * blockDim.x + threadIdx.x;
    if (i < n) { g_cnt[i] = 0; g_cursor[i] = 0; }
    if (i == 0) out[0] = 0.0f;
}

// ---------------- in-degree histogram ----------------
__global__ void hist_kernel(const int* __restrict__ dst, int e) {
    int i = blockIdx.x * blockDim.x + threadIdx.x;
    if (i < e) atomicAdd(&g_cnt[dst[i]], 1);
}

// ---------------- dinv = rsqrt(deg + 1 self loop) ----------------
__global__ void dinv_kernel(int n) {
    int i = blockIdx.x * blockDim.x + threadIdx.x;
    if (i < n) g_dinv[i] = rsqrtf((float)(g_cnt[i] + 1));
}

// ---------------- single-block exclusive scan over g_cnt -> g_rowstart ----------------
__global__ void scan_kernel(int n) {
    __shared__ int warp_off[32];
    __shared__ int s_carry;
    __shared__ int s_total;
    int tid = threadIdx.x;
    if (tid == 0) s_carry = 0;
    __syncthreads();
    for (int base = 0; base < n; base += 1024) {
        int i = base + tid;
        int v = (i < n) ? g_cnt[i] : 0;
        // warp inclusive scan
        int x = v;
        #pragma unroll
        for (int o = 1; o < 32; o <<= 1) {
            int t = __shfl_up_sync(0xffffffffu, x, o);
            if ((tid & 31) >= o) x += t;
        }
        if ((tid & 31) == 31) warp_off[tid >> 5] = x;
        __syncthreads();
        if (tid < 32) {
            int w = warp_off[tid];
            int y = w;
            #pragma unroll
            for (int o = 1; o < 32; o <<= 1) {
                int t = __shfl_up_sync(0xffffffffu, y, o);
                if (tid >= o) y += t;
            }
            warp_off[tid] = y - w;           // exclusive warp offset
            if (tid == 31) s_total = y;      // block total
        }
        __syncthreads();
        int incl = x + warp_off[tid >> 5];
        int carry = s_carry;
        if (i < n) g_rowstart[i] = carry + incl - v;
        __syncthreads();
        if (tid == 0) s_carry = carry + s_total;
        __syncthreads();
    }
    if (tid == 0) g_rowstart[n] = s_carry;
}

// ---------------- fill CSR: edges grouped by dst, store src ----------------
__global__ void fill_kernel(const int* __restrict__ src, const int* __restrict__ dst, int e) {
    int i = blockIdx.x * blockDim.x + threadIdx.x;
    if (i < e) {
        int d = dst[i];
        int p = atomicAdd(&g_cursor[d], 1);
        g_csr[g_rowstart[d] + p] = src[i];
    }
}

// ---------------- tiled FP32 GEMM: C = A[M,K] * B[K,N] (+bias, relu) ----------------
// threads = (BM/TM)*(BN/TN) = 256
template<int BM, int BN, int BK, int TM, int TN, bool EPI>
__global__ void gemm_kernel(const float* __restrict__ A, const float* __restrict__ B,
                            const float* __restrict__ bias, float* __restrict__ C,
                            int M, int N, int K) {
    __shared__ float As[BK][BM];
    __shared__ float Bs[BK][BN];
    const int tid = threadIdx.x;
    const int TX = BN / TN;
    const int tx = tid % TX;
    const int ty = tid / TX;
    const int row0 = blockIdx.y * BM;
    const int col0 = blockIdx.x * BN;

    float acc[TM][TN];
    #pragma unroll
    for (int i = 0; i < TM; i++)
        #pragma unroll
        for (int j = 0; j < TN; j++) acc[i][j] = 0.0f;

    for (int k0 = 0; k0 < K; k0 += BK) {
        // load A tile (transpose into As[k][m])
        #pragma unroll
        for (int it = tid; it < BM * BK; it += 256) {
            int r = it / BK, c = it % BK;
            int gr = row0 + r;
            As[c][r] = (gr < M) ? A[(size_t)gr * K + k0 + c] : 0.0f;
        }
        // load B tile
        #pragma unroll
        for (int it = tid; it < BK * BN; it += 256) {
            int r = it / BN, c = it % BN;
            Bs[r][c] = B[(size_t)(k0 + r) * N + col0 + c];
        }
        __syncthreads();
        #pragma unroll
        for (int k = 0; k < BK; k++) {
            float a[TM], b[TN];
            #pragma unroll
            for (int i = 0; i < TM; i++) a[i] = As[k][ty * TM + i];
            #pragma unroll
            for (int j = 0; j < TN; j++) b[j] = Bs[k][tx * TN + j];
            #pragma unroll
            for (int i = 0; i < TM; i++)
                #pragma unroll
                for (int j = 0; j < TN; j++) acc[i][j] = fmaf(a[i], b[j], acc[i][j]);
        }
        __syncthreads();
    }
    #pragma unroll
    for (int i = 0; i < TM; i++) {
        int gr = row0 + ty * TM + i;
        if (gr < M) {
            #pragma unroll
            for (int j = 0; j < TN; j++) {
                int gc = col0 + tx * TN + j;
                float v = acc[i][j];
                if (EPI) { v += bias[gc]; v = fmaxf(v, 0.0f); }
                C[(size_t)gr * N + gc] = v;
            }
        }
    }
}

// ---------------- 64-dim normalized aggregation via CSR gather ----------------
// out[i] = dinv[i]^2 * in[i] + sum_{j in N_in(i)} dinv[j]*dinv[i]*in[j]  (+bias, relu)
// one 16-lane group per node, float4 per lane
template<bool RELU>
__global__ void agg64_kernel(const float4* __restrict__ in4, float4* __restrict__ out4,
                             const float4* __restrict__ bias4, int n) {
    int g = blockIdx.x * blockDim.x + threadIdx.x;
    int node = g >> 4;
    int sub  = g & 15;
    if (node >= n) return;
    float di = g_dinv[node];
    float4 self = in4[(size_t)node * 16 + sub];
    float w0 = di * di;
    float4 acc;
    acc.x = self.x * w0; acc.y = self.y * w0; acc.z = self.z * w0; acc.w = self.w * w0;
    int s0 = g_rowstart[node], s1 = g_rowstart[node + 1];
    for (int j = s0; j < s1; j++) {
        int s = __ldg(&g_csr[j]);
        float w = g_dinv[s] * di;
        float4 v = in4[(size_t)s * 16 + sub];
        acc.x = fmaf(w, v.x, acc.x);
        acc.y = fmaf(w, v.y, acc.y);
        acc.z = fmaf(w, v.z, acc.z);
        acc.w = fmaf(w, v.w, acc.w);
    }
    if (RELU) {
        float4 b = bias4[sub];
        acc.x = fmaxf(acc.x + b.x, 0.0f);
        acc.y = fmaxf(acc.y + b.y, 0.0f);
        acc.z = fmaxf(acc.z + b.z, 0.0f);
        acc.w = fmaxf(acc.w + b.w, 0.0f);
    }
    out4[(size_t)node * 16 + sub] = acc;
}

// ---------------- xw3 = h2 @ W3 (row dot, warp per node); z init with self term ----------------
__global__ void rowdot_z_kernel(const float* __restrict__ h2, const float* __restrict__ W3, int n) {
    int t = blockIdx.x * blockDim.x + threadIdx.x;
    int node = t >> 5;
    int lane = t & 31;
    if (node >= n) return;
    const float* r = h2 + (size_t)node * D2;
    float s = 0.0f;
    #pragma unroll
    for (int i = 0; i < 8; i++) {
        int k = lane + 32 * i;
        s = fmaf(r[k], W3[k], s);
    }
    #pragma unroll
    for (int o = 16; o; o >>= 1) s += __shfl_xor_sync(0xffffffffu, s, o);
    if (lane == 0) {
        g_xw3[node] = s;
        float di = g_dinv[node];
        g_z[node] = di * di * s;
    }
}

// ---------------- scalar aggregation of xw3 into z, then fused BCE loss reduce ----------------
__global__ void aggz_loss_kernel(const float* __restrict__ y, const float* __restrict__ b3,
                                 float* __restrict__ out, int n) {
    int i = blockIdx.x * blockDim.x + threadIdx.x;
    float l = 0.0f;
    if (i < n) {
        float di = g_dinv[i];
        float acc = g_z[i];
        for (int j = g_rowstart[i]; j < g_rowstart[i + 1]; j++) {
            int s = g_csr[j];
            acc = fmaf(g_dinv[s] * di, g_xw3[s], acc);
        }
        float z = acc + b3[0];
        // loss = softplus(z) - y*z  (stable)
        float sp = fmaxf(z, 0.0f) + log1pf(expf(-fabsf(z)));
        l = sp - y[i] * z;
    }
    __shared__ float red[256];
    red[threadIdx.x] = l;
    __syncthreads();
    #pragma unroll
    for (int o = 128; o; o >>= 1) {
        if (threadIdx.x < o) red[threadIdx.x] += red[threadIdx.x + o];
        __syncthreads();
    }
    if (threadIdx.x == 0) atomicAdd(out, red[0] * (1.0f / (float)n));
}

// ---------------- launch ----------------
extern "C" void kernel_launch(void* const* d_in, const int* in_sizes, int n_in,
                              void* d_out, int out_size) {
    const float* x   = (const float*)d_in[0];
    const int*   ei  = (const int*)d_in[1];
    const float* y   = (const float*)d_in[2];
    const float* W1  = (const float*)d_in[3];
    const float* b1  = (const float*)d_in[4];
    const float* W2  = (const float*)d_in[5];
    const float* b2  = (const float*)d_in[6];
    const float* W3  = (const float*)d_in[7];
    const float* b3  = (const float*)d_in[8];
    float* out = (float*)d_out;

    int n = in_sizes[0] / F0;      // 100000
    int e = in_sizes[1] / 2;       // 1600000
    const int* src = ei;
    const int* dst = ei + e;

    void *p_xw1, *p_h1, *p_a2, *p_h2;
    cudaGetSymbolAddress(&p_xw1, g_xw1);
    cudaGetSymbolAddress(&p_h1,  g_h1);
    cudaGetSymbolAddress(&p_a2,  g_a2);
    cudaGetSymbolAddress(&p_h2,  g_h2);

    // graph structure
    init_kernel<<<(n + 255) / 256, 256>>>(out, n);
    hist_kernel<<<(e + 255) / 256, 256>>>(dst, e);
    dinv_kernel<<<(n + 255) / 256, 256>>>(n);
    scan_kernel<<<1, 1024>>>(n);
    fill_kernel<<<(e + 255) / 256, 256>>>(src, dst, e);

    // layer 1: GEMM (512->64) then aggregate 64-dim with fused bias+relu
    gemm_kernel<128, 64, 16, 4, 8, false><<<dim3(1, (n + 127) / 128), 256>>>(
        x, W1, nullptr, (float*)p_xw1, n, D1, F0);
    agg64_kernel<true><<<(n * 16 + 255) / 256, 256>>>(
        (const float4*)p_xw1, (float4*)p_h1, (const float4*)b1, n);

    // layer 2: aggregate 64-dim first, then GEMM (64->256) with fused bias+relu
    agg64_kernel<false><<<(n * 16 + 255) / 256, 256>>>(
        (const float4*)p_h1, (float4*)p_a2, nullptr, n);
    gemm_kernel<64, 128, 16, 4, 8, true><<<dim3(2, (n + 63) / 64), 256>>>(
        (const float*)p_a2, W2, b2, (float*)p_h2, n, D2, D1);

    // layer 3: row dot (256->1), scalar aggregation fused with BCE loss
    rowdot_z_kernel<<<(n * 32 + 255) / 256, 256>>>((const float*)p_h2, W3, n);
    aggz_loss_kernel<<<(n + 255) / 256, 256>>>(y, b3, out, n);
}

// round 3
// speedup vs baseline: 3.3316x; 3.3316x over previous
#include <cuda_runtime.h>
#include <cuda_bf16.h>
#include <math.h>
#include <stdint.h>

// ---------------- static problem sizes ----------------
#define NN  100000
#define EE  1600000
#define F0  512
#define D1  64
#define D2  256
#define NB_SCAN ((NN + 255) / 256)   // 391

// ---------------- device scratch ----------------
__device__ float g_dinv[NN];
__device__ int   g_cnt[NN];
__device__ int   g_rowstart[NN + 1];
__device__ int   g_cursor[NN];
__device__ int   g_csr[EE];
__device__ int   g_bsum[512];
__device__ float g_xw1[(size_t)NN * D1];
__device__ float g_h1 [(size_t)NN * D1];
__device__ float g_a2 [(size_t)NN * D1];
__device__ float g_h2 [(size_t)NN * D2];
__device__ float g_xw3[NN];
__device__ float g_z  [NN];

// ---------------- init ----------------
__global__ void init_kernel(float* out, int n) {
    int i = blockIdx.x * blockDim.x + threadIdx.x;
    if (i < n) { g_cnt[i] = 0; g_cursor[i] = 0; }
    if (i == 0) out[0] = 0.0f;
}

__global__ void hist_kernel(const int* __restrict__ dst, int e) {
    int i = blockIdx.x * blockDim.x + threadIdx.x;
    if (i < e) atomicAdd(&g_cnt[dst[i]], 1);
}

__global__ void dinv_kernel(int n) {
    int i = blockIdx.x * blockDim.x + threadIdx.x;
    if (i < n) g_dinv[i] = rsqrtf((float)(g_cnt[i] + 1));
}

// ---------------- 3-stage full-chip scan ----------------
__global__ void bsum_kernel(int n) {
    __shared__ int wsum[8];
    int i = blockIdx.x * 256 + threadIdx.x;
    int v = (i < n) ? g_cnt[i] : 0;
    #pragma unroll
    for (int o = 16; o; o >>= 1) v += __shfl_xor_sync(0xffffffffu, v, o);
    if ((threadIdx.x & 31) == 0) wsum[threadIdx.x >> 5] = v;
    __syncthreads();
    if (threadIdx.x == 0) {
        int s = 0;
        #pragma unroll
        for (int w = 0; w < 8; w++) s += wsum[w];
        g_bsum[blockIdx.x] = s;
    }
}

__global__ void bscan_kernel(int nb, int n) {
    __shared__ int s[512];
    int t = threadIdx.x;
    int orig = (t < nb) ? g_bsum[t] : 0;
    s[t] = orig;
    __syncthreads();
    #pragma unroll
    for (int o = 1; o < 512; o <<= 1) {
        int v = (t >= o) ? s[t - o] : 0;
        __syncthreads();
        s[t] += v;
        __syncthreads();
    }
    if (t < nb) g_bsum[t] = s[t] - orig;          // exclusive block offsets
    if (t == 0) g_rowstart[n] = s[511];           // total edges
}

__global__ void rowstart_kernel(int n) {
    __shared__ int warp_off[8];
    int tid = threadIdx.x;
    int i = blockIdx.x * 256 + tid;
    int v = (i < n) ? g_cnt[i] : 0;
    int x = v;
    #pragma unroll
    for (int o = 1; o < 32; o <<= 1) {
        int t = __shfl_up_sync(0xffffffffu, x, o);
        if ((tid & 31) >= o) x += t;
    }
    if ((tid & 31) == 31) warp_off[tid >> 5] = x;
    __syncthreads();
    if (tid < 8) {
        int w = warp_off[tid];
        int y = w;
        #pragma unroll
        for (int o = 1; o < 8; o <<= 1) {
            int t = __shfl_up_sync(0xffu, y, o);
            if (tid >= o) y += t;
        }
        warp_off[tid] = y - w;
    }
    __syncthreads();
    if (i < n) g_rowstart[i] = g_bsum[blockIdx.x] + x - v + warp_off[tid >> 5];
}

__global__ void fill_kernel(const int* __restrict__ src, const int* __restrict__ dst, int e) {
    int i = blockIdx.x * blockDim.x + threadIdx.x;
    if (i < e) {
        int d = dst[i];
        int p = atomicAdd(&g_cursor[d], 1);
        g_csr[g_rowstart[d] + p] = src[i];
    }
}

// ---------------- tensor-core bf16 GEMM ----------------
__device__ __forceinline__ uint32_t smem_u32(const void* p) {
    return (uint32_t)__cvta_generic_to_shared(p);
}
__device__ __forceinline__ void ldsm_x4(uint32_t& r0, uint32_t& r1, uint32_t& r2, uint32_t& r3, uint32_t a) {
    asm volatile("ldmatrix.sync.aligned.m8n8.x4.shared.b16 {%0,%1,%2,%3}, [%4];\n"
                 : "=r"(r0), "=r"(r1), "=r"(r2), "=r"(r3) : "r"(a));
}
__device__ __forceinline__ void ldsm_x4_t(uint32_t& r0, uint32_t& r1, uint32_t& r2, uint32_t& r3, uint32_t a) {
    asm volatile("ldmatrix.sync.aligned.m8n8.x4.trans.shared.b16 {%0,%1,%2,%3}, [%4];\n"
                 : "=r"(r0), "=r"(r1), "=r"(r2), "=r"(r3) : "r"(a));
}
__device__ __forceinline__ void mma_bf16(float* c, const uint32_t* a, const uint32_t* b) {
    asm volatile(
        "mma.sync.aligned.m16n8k16.row.col.f32.bf16.bf16.f32 "
        "{%0,%1,%2,%3}, {%4,%5,%6,%7}, {%8,%9}, {%0,%1,%2,%3};\n"
        : "+f"(c[0]), "+f"(c[1]), "+f"(c[2]), "+f"(c[3])
        : "r"(a[0]), "r"(a[1]), "r"(a[2]), "r"(a[3]), "r"(b[0]), "r"(b[1]));
}

// C[M,N] = A[M,K]fp32 @ B[K,N]fp32, bf16 tensor cores, fp32 accum.
// BM=128 BN=64 BK=64, 256 threads (8 warps: 4 along M x 2 along N, 32x32 warp tiles)
template<bool EPI>
__global__ void __launch_bounds__(256)
gemm_tc_kernel(const float* __restrict__ A, const float* __restrict__ B,
               const float* __restrict__ bias, float* __restrict__ C,
               int M, int N, int K) {
    __shared__ __align__(16) __nv_bfloat16 As[128][72];
    __shared__ __align__(16) __nv_bfloat16 Bs[64][72];
    const int tid = threadIdx.x, lane = tid & 31, w = tid >> 5;
    const int wm = (w & 3) * 32, wn = (w >> 2) * 32;
    const int row0 = blockIdx.y * 128, col0 = blockIdx.x * 64;

    float acc[2][4][4];
    #pragma unroll
    for (int mt = 0; mt < 2; mt++)
        #pragma unroll
        for (int nt = 0; nt < 4; nt++)
            #pragma unroll
            for (int r = 0; r < 4; r++) acc[mt][nt][r] = 0.0f;

    for (int k0 = 0; k0 < K; k0 += 64) {
        // stage A tile (128 x 64), convert fp32 -> bf16
        #pragma unroll
        for (int i = 0; i < 8; i++) {
            int idx = tid + i * 256;
            int r = idx >> 4, cq = idx & 15;
            float4 v = make_float4(0.f, 0.f, 0.f, 0.f);
            int gr = row0 + r;
            if (gr < M) v = *(const float4*)&A[(size_t)gr * K + k0 + cq * 4];
            *(__nv_bfloat162*)&As[r][cq * 4]     = __floats2bfloat162_rn(v.x, v.y);
            *(__nv_bfloat162*)&As[r][cq * 4 + 2] = __floats2bfloat162_rn(v.z, v.w);
        }
        // stage B tile (64 x 64)
        #pragma unroll
        for (int i = 0; i < 4; i++) {
            int idx = tid + i * 256;
            int r = idx >> 4, cq = idx & 15;
            float4 v = *(const float4*)&B[(size_t)(k0 + r) * N + col0 + cq * 4];
            *(__nv_bfloat162*)&Bs[r][cq * 4]     = __floats2bfloat162_rn(v.x, v.y);
            *(__nv_bfloat162*)&Bs[r][cq * 4 + 2] = __floats2bfloat162_rn(v.z, v.w);
        }
        __syncthreads();
        #pragma unroll
        for (int ks = 0; ks < 4; ks++) {
            uint32_t a[2][4];
            #pragma unroll
            for (int mt = 0; mt < 2; mt++) {
                int rrow = wm + mt * 16 + (lane & 7) + ((lane >> 3) & 1) * 8;
                int ccol = ks * 16 + (lane >> 4) * 8;
                ldsm_x4(a[mt][0], a[mt][1], a[mt][2], a[mt][3], smem_u32(&As[rrow][ccol]));
            }
            uint32_t b[4][2];
            #pragma unroll
            for (int pr = 0; pr < 2; pr++) {
                int kk = ks * 16 + ((lane >> 3) & 1) * 8 + (lane & 7);
                int nn = wn + pr * 16 + (lane >> 4) * 8;
                uint32_t r0, r1, r2, r3;
                ldsm_x4_t(r0, r1, r2, r3, smem_u32(&Bs[kk][nn]));
                b[pr * 2][0] = r0; b[pr * 2][1] = r1;
                b[pr * 2 + 1][0] = r2; b[pr * 2 + 1][1] = r3;
            }
            #pragma unroll
            for (int mt = 0; mt < 2; mt++)
                #pragma unroll
                for (int nt = 0; nt < 4; nt++)
                    mma_bf16(acc[mt][nt], a[mt], b[nt]);
        }
        __syncthreads();
    }
    // epilogue
    #pragma unroll
    for (int mt = 0; mt < 2; mt++) {
        int r_lo = row0 + wm + mt * 16 + (lane >> 2);
        #pragma unroll
        for (int nt = 0; nt < 4; nt++) {
            int c = col0 + wn + nt * 8 + (lane & 3) * 2;
            float v0 = acc[mt][nt][0], v1 = acc[mt][nt][1];
            float v2 = acc[mt][nt][2], v3 = acc[mt][nt][3];
            if (EPI) {
                float b0 = bias[c], b1 = bias[c + 1];
                v0 = fmaxf(v0 + b0, 0.f); v1 = fmaxf(v1 + b1, 0.f);
                v2 = fmaxf(v2 + b0, 0.f); v3 = fmaxf(v3 + b1, 0.f);
            }
            if (r_lo < M) {
                C[(size_t)r_lo * N + c] = v0;
                C[(size_t)r_lo * N + c + 1] = v1;
            }
            if (r_lo + 8 < M) {
                C[(size_t)(r_lo + 8) * N + c] = v2;
                C[(size_t)(r_lo + 8) * N + c + 1] = v3;
            }
        }
    }
}

// ---------------- 64-dim normalized aggregation (CSR gather) ----------------
template<bool RELU>
__global__ void agg64_kernel(const float4* __restrict__ in4, float4* __restrict__ out4,
                             const float4* __restrict__ bias4, int n) {
    int g = blockIdx.x * blockDim.x + threadIdx.x;
    int node = g >> 4;
    int sub  = g & 15;
    if (node >= n) return;
    float di = g_dinv[node];
    float4 self = in4[(size_t)node * 16 + sub];
    float w0 = di * di;
    float4 acc;
    acc.x = self.x * w0; acc.y = self.y * w0; acc.z = self.z * w0; acc.w = self.w * w0;
    int s0 = g_rowstart[node], s1 = g_rowstart[node + 1];
    for (int j = s0; j < s1; j++) {
        int s = __ldg(&g_csr[j]);
        float wgt = g_dinv[s] * di;
        float4 v = in4[(size_t)s * 16 + sub];
        acc.x = fmaf(wgt, v.x, acc.x);
        acc.y = fmaf(wgt, v.y, acc.y);
        acc.z = fmaf(wgt, v.z, acc.z);
        acc.w = fmaf(wgt, v.w, acc.w);
    }
    if (RELU) {
        float4 b = bias4[sub];
        acc.x = fmaxf(acc.x + b.x, 0.f);
        acc.y = fmaxf(acc.y + b.y, 0.f);
        acc.z = fmaxf(acc.z + b.z, 0.f);
        acc.w = fmaxf(acc.w + b.w, 0.f);
    }
    out4[(size_t)node * 16 + sub] = acc;
}

// ---------------- layer 3: row dot + self term ----------------
__global__ void rowdot_z_kernel(const float* __restrict__ h2, const float* __restrict__ W3, int n) {
    int t = blockIdx.x * blockDim.x + threadIdx.x;
    int node = t >> 5;
    int lane = t & 31;
    if (node >= n) return;
    const float* r = h2 + (size_t)node * D2;
    float s = 0.0f;
    #pragma unroll
    for (int i = 0; i < 8; i++) {
        int k = lane + 32 * i;
        s = fmaf(r[k], W3[k], s);
    }
    #pragma unroll
    for (int o = 16; o; o >>= 1) s += __shfl_xor_sync(0xffffffffu, s, o);
    if (lane == 0) {
        g_xw3[node] = s;
        float di = g_dinv[node];
        g_z[node] = di * di * s;
    }
}

// ---------------- scalar aggregation + fused BCE loss ----------------
__global__ void aggz_loss_kernel(const float* __restrict__ y, const float* __restrict__ b3,
                                 float* __restrict__ out, int n) {
    int i = blockIdx.x * blockDim.x + threadIdx.x;
    float l = 0.0f;
    if (i < n) {
        float di = g_dinv[i];
        float acc = g_z[i];
        for (int j = g_rowstart[i]; j < g_rowstart[i + 1]; j++) {
            int s = g_csr[j];
            acc = fmaf(g_dinv[s] * di, g_xw3[s], acc);
        }
        float z = acc + b3[0];
        float sp = fmaxf(z, 0.0f) + log1pf(expf(-fabsf(z)));
        l = sp - y[i] * z;
    }
    __shared__ float red[256];
    red[threadIdx.x] = l;
    __syncthreads();
    #pragma unroll
    for (int o = 128; o; o >>= 1) {
        if (threadIdx.x < o) red[threadIdx.x] += red[threadIdx.x + o];
        __syncthreads();
    }
    if (threadIdx.x == 0) atomicAdd(out, red[0] * (1.0f / (float)n));
}

// ---------------- launch ----------------
extern "C" void kernel_launch(void* const* d_in, const int* in_sizes, int n_in,
                              void* d_out, int out_size) {
    const float* x   = (const float*)d_in[0];
    const int*   ei  = (const int*)d_in[1];
    const float* y   = (const float*)d_in[2];
    const float* W1  = (const float*)d_in[3];
    const float* b1  = (const float*)d_in[4];
    const float* W2  = (const float*)d_in[5];
    const float* b2  = (const float*)d_in[6];
    const float* W3  = (const float*)d_in[7];
    const float* b3  = (const float*)d_in[8];
    float* out = (float*)d_out;

    int n = in_sizes[0] / F0;      // 100000
    int e = in_sizes[1] / 2;       // 1600000
    const int* src = ei;
    const int* dst = ei + e;

    void *p_xw1, *p_h1, *p_a2, *p_h2;
    cudaGetSymbolAddress(&p_xw1, g_xw1);
    cudaGetSymbolAddress(&p_h1,  g_h1);
    cudaGetSymbolAddress(&p_a2,  g_a2);
    cudaGetSymbolAddress(&p_h2,  g_h2);

    static cudaStream_t s2 = nullptr;
    static cudaEvent_t evA = nullptr, evB = nullptr;
    if (!s2) {
        cudaStreamCreateWithFlags(&s2, cudaStreamNonBlocking);
        cudaEventCreateWithFlags(&evA, cudaEventDisableTiming);
        cudaEventCreateWithFlags(&evB, cudaEventDisableTiming);
    }

    int nb = (n + 255) / 256;

    // fork: gemm1 (x @ W1, independent of graph structure) on s2
    cudaEventRecord(evA, 0);
    cudaStreamWaitEvent(s2, evA, 0);
    gemm_tc_kernel<false><<<dim3(1, (n + 127) / 128), 256, 0, s2>>>(
        x, W1, nullptr, (float*)p_xw1, n, D1, F0);
    cudaEventRecord(evB, s2);

    // stream 0: graph structure build
    init_kernel<<<(n + 255) / 256, 256>>>(out, n);
    hist_kernel<<<(e + 255) / 256, 256>>>(dst, e);
    dinv_kernel<<<(n + 255) / 256, 256>>>(n);
    bsum_kernel<<<nb, 256>>>(n);
    bscan_kernel<<<1, 512>>>(nb, n);
    rowstart_kernel<<<nb, 256>>>(n);
    fill_kernel<<<(e + 255) / 256, 256>>>(src, dst, e);

    // join
    cudaStreamWaitEvent(0, evB, 0);

    // layer 1 aggregation (fused bias + relu)
    agg64_kernel<true><<<(n * 16 + 255) / 256, 256>>>(
        (const float4*)p_xw1, (float4*)p_h1, (const float4*)b1, n);

    // layer 2: aggregate first (64-dim), then GEMM 64->256 with fused bias+relu
    agg64_kernel<false><<<(n * 16 + 255) / 256, 256>>>(
        (const float4*)p_h1, (float4*)p_a2, nullptr, n);
    gemm_tc_kernel<true><<<dim3(4, (n + 127) / 128), 256>>>(
        (const float*)p_a2, W2, b2, (float*)p_h2, n, D2, D1);

    // layer 3: row dot (256->1), scalar aggregation fused with BCE loss
    rowdot_z_kernel<<<(n * 32 + 255) / 256, 256>>>((const float*)p_h2, W3, n);
    aggz_loss_kernel<<<(n + 255) / 256, 256>>>(y, b3, out, n);
}

// round 4
// speedup vs baseline: 3.9153x; 1.1752x over previous
#include <cuda_runtime.h>
#include <cuda_bf16.h>
#include <math.h>
#include <stdint.h>

// ---------------- static problem sizes ----------------
#define NN  100000
#define EE  1600000
#define F0  512
#define D1  64
#define D2  256

// ---------------- device scratch ----------------
__device__ float g_dinv[NN];
__device__ int   g_cnt[NN];
__device__ int   g_rowstart[NN + 1];
__device__ int   g_cursor[NN];
__device__ int   g_csr[EE];
__device__ int   g_bsum[512];
__device__ __nv_bfloat16 g_xw1[(size_t)NN * D1];
__device__ __nv_bfloat16 g_h1 [(size_t)NN * D1];
__device__ __nv_bfloat16 g_a2 [(size_t)NN * D1];
__device__ __nv_bfloat16 g_h2 [(size_t)NN * D2];
__device__ float g_xw3[NN];
__device__ float g_z  [NN];

// ---------------- init: zero counters + output ----------------
__global__ void init_kernel(float* out, int n) {
    int i = blockIdx.x * blockDim.x + threadIdx.x;
    if (i < n) g_cnt[i] = 0;
    if (i == 0) out[0] = 0.0f;
}

__global__ void hist_kernel(const int* __restrict__ dst, int e) {
    int i = blockIdx.x * blockDim.x + threadIdx.x;
    if (i < e) atomicAdd(&g_cnt[dst[i]], 1);
}

// ---------------- dinv + per-block sums (fused) ----------------
__global__ void bsumdinv_kernel(int n) {
    __shared__ int wsum[8];
    int i = blockIdx.x * 256 + threadIdx.x;
    int v = (i < n) ? g_cnt[i] : 0;
    if (i < n) g_dinv[i] = rsqrtf((float)(v + 1));
    int s = v;
    #pragma unroll
    for (int o = 16; o; o >>= 1) s += __shfl_xor_sync(0xffffffffu, s, o);
    if ((threadIdx.x & 31) == 0) wsum[threadIdx.x >> 5] = s;
    __syncthreads();
    if (threadIdx.x == 0) {
        int t = 0;
        #pragma unroll
        for (int w = 0; w < 8; w++) t += wsum[w];
        g_bsum[blockIdx.x] = t;
    }
}

__global__ void bscan_kernel(int nb, int n) {
    __shared__ int s[512];
    int t = threadIdx.x;
    int orig = (t < nb) ? g_bsum[t] : 0;
    s[t] = orig;
    __syncthreads();
    #pragma unroll
    for (int o = 1; o < 512; o <<= 1) {
        int v = (t >= o) ? s[t - o] : 0;
        __syncthreads();
        s[t] += v;
        __syncthreads();
    }
    if (t < nb) g_bsum[t] = s[t] - orig;
    if (t == 0) g_rowstart[n] = s[511];
}

__global__ void rowstart_kernel(int n) {
    __shared__ int warp_off[8];
    int tid = threadIdx.x;
    int i = blockIdx.x * 256 + tid;
    int v = (i < n) ? g_cnt[i] : 0;
    int x = v;
    #pragma unroll
    for (int o = 1; o < 32; o <<= 1) {
        int t = __shfl_up_sync(0xffffffffu, x, o);
        if ((tid & 31) >= o) x += t;
    }
    if ((tid & 31) == 31) warp_off[tid >> 5] = x;
    __syncthreads();
    if (tid < 8) {
        int w = warp_off[tid];
        int y = w;
        #pragma unroll
        for (int o = 1; o < 8; o <<= 1) {
            int t = __shfl_up_sync(0xffu, y, o);
            if (tid >= o) y += t;
        }
        warp_off[tid] = y - w;
    }
    __syncthreads();
    if (i < n) {
        int rs = g_bsum[blockIdx.x] + x - v + warp_off[tid >> 5];
        g_rowstart[i] = rs;
        g_cursor[i] = rs;   // fill() atomics directly on cursor = absolute position
    }
}

__global__ void fill_kernel(const int* __restrict__ src, const int* __restrict__ dst, int e) {
    int i = blockIdx.x * blockDim.x + threadIdx.x;
    if (i < e) {
        int p = atomicAdd(&g_cursor[dst[i]], 1);
        g_csr[p] = src[i];
    }
}

// ---------------- tensor-core bf16 GEMM (fp32 or bf16 A input, bf16 output) ----------------
__device__ __forceinline__ uint32_t smem_u32(const void* p) {
    return (uint32_t)__cvta_generic_to_shared(p);
}
__device__ __forceinline__ void ldsm_x4(uint32_t& r0, uint32_t& r1, uint32_t& r2, uint32_t& r3, uint32_t a) {
    asm volatile("ldmatrix.sync.aligned.m8n8.x4.shared.b16 {%0,%1,%2,%3}, [%4];\n"
                 : "=r"(r0), "=r"(r1), "=r"(r2), "=r"(r3) : "r"(a));
}
__device__ __forceinline__ void ldsm_x4_t(uint32_t& r0, uint32_t& r1, uint32_t& r2, uint32_t& r3, uint32_t a) {
    asm volatile("ldmatrix.sync.aligned.m8n8.x4.trans.shared.b16 {%0,%1,%2,%3}, [%4];\n"
                 : "=r"(r0), "=r"(r1), "=r"(r2), "=r"(r3) : "r"(a));
}
__device__ __forceinline__ void mma_bf16(float* c, const uint32_t* a, const uint32_t* b) {
    asm volatile(
        "mma.sync.aligned.m16n8k16.row.col.f32.bf16.bf16.f32 "
        "{%0,%1,%2,%3}, {%4,%5,%6,%7}, {%8,%9}, {%0,%1,%2,%3};\n"
        : "+f"(c[0]), "+f"(c[1]), "+f"(c[2]), "+f"(c[3])
        : "r"(a[0]), "r"(a[1]), "r"(a[2]), "r"(a[3]), "r"(b[0]), "r"(b[1]));
}

// BM=128 BN=64 BK=64, 256 threads (8 warps: 4 x M, 2 x N; 32x32 warp tiles)
// Register double-buffering on global loads.
template<typename TA, bool EPI>
__global__ void __launch_bounds__(256)
gemm_tc_kernel(const TA* __restrict__ A, const float* __restrict__ B,
               const float* __restrict__ bias, __nv_bfloat16* __restrict__ C,
               int M, int N, int K) {
    __shared__ __align__(16) __nv_bfloat16 As[128][72];
    __shared__ __align__(16) __nv_bfloat16 Bs[64][72];
    const int tid = threadIdx.x, lane = tid & 31, w = tid >> 5;
    const int wm = (w & 3) * 32, wn = (w >> 2) * 32;
    const int row0 = blockIdx.y * 128, col0 = blockIdx.x * 64;

    constexpr bool A_F32 = sizeof(TA) == 4;

    float acc[2][4][4];
    #pragma unroll
    for (int mt = 0; mt < 2; mt++)
        #pragma unroll
        for (int nt = 0; nt < 4; nt++)
            #pragma unroll
            for (int r = 0; r < 4; r++) acc[mt][nt][r] = 0.0f;

    float4 a_f[8]; uint4 a_h[4]; float4 b_f[4];

    auto load_regs = [&](int k0) {
        if constexpr (A_F32) {
            #pragma unroll
            for (int i = 0; i < 8; i++) {
                int idx = tid + i * 256;
                int r = idx >> 4, cq = idx & 15;
                int gr = row0 + r;
                a_f[i] = (gr < M) ? *(const float4*)&A[(size_t)gr * K + k0 + cq * 4]
                                  : make_float4(0.f, 0.f, 0.f, 0.f);
            }
        } else {
            #pragma unroll
            for (int i = 0; i < 4; i++) {
                int idx = tid + i * 256;
                int r = idx >> 3, q = idx & 7;
                int gr = row0 + r;
                a_h[i] = (gr < M) ? *(const uint4*)&A[(size_t)gr * K + k0 + q * 8]
                                  : make_uint4(0u, 0u, 0u, 0u);
            }
        }
        #pragma unroll
        for (int i = 0; i < 4; i++) {
            int idx = tid + i * 256;
            int r = idx >> 4, cq = idx & 15;
            b_f[i] = *(const float4*)&B[(size_t)(k0 + r) * N + col0 + cq * 4];
        }
    };
    auto store_smem = [&]() {
        if constexpr (A_F32) {
            #pragma unroll
            for (int i = 0; i < 8; i++) {
                int idx = tid + i * 256;
                int r = idx >> 4, cq = idx & 15;
                *(__nv_bfloat162*)&As[r][cq * 4]     = __floats2bfloat162_rn(a_f[i].x, a_f[i].y);
                *(__nv_bfloat162*)&As[r][cq * 4 + 2] = __floats2bfloat162_rn(a_f[i].z, a_f[i].w);
            }
        } else {
            #pragma unroll
            for (int i = 0; i < 4; i++) {
                int idx = tid + i * 256;
                int r = idx >> 3, q = idx & 7;
                *(uint4*)&As[r][q * 8] = a_h[i];
            }
        }
        #pragma unroll
        for (int i = 0; i < 4; i++) {
            int idx = tid + i * 256;
            int r = idx >> 4, cq = idx & 15;
            *(__nv_bfloat162*)&Bs[r][cq * 4]     = __floats2bfloat162_rn(b_f[i].x, b_f[i].y);
            *(__nv_bfloat162*)&Bs[r][cq * 4 + 2] = __floats2bfloat162_rn(b_f[i].z, b_f[i].w);
        }
    };

    load_regs(0);
    for (int k0 = 0; k0 < K; k0 += 64) {
        store_smem();
        __syncthreads();
        if (k0 + 64 < K) load_regs(k0 + 64);   // prefetch next tile while MMAs run
        #pragma unroll
        for (int ks = 0; ks < 4; ks++) {
            uint32_t a[2][4];
            #pragma unroll
            for (int mt = 0; mt < 2; mt++) {
                int rrow = wm + mt * 16 + (lane & 7) + ((lane >> 3) & 1) * 8;
                int ccol = ks * 16 + (lane >> 4) * 8;
                ldsm_x4(a[mt][0], a[mt][1], a[mt][2], a[mt][3], smem_u32(&As[rrow][ccol]));
            }
            uint32_t b[4][2];
            #pragma unroll
            for (int pr = 0; pr < 2; pr++) {
                int kk = ks * 16 + ((lane >> 3) & 1) * 8 + (lane & 7);
                int nn = wn + pr * 16 + (lane >> 4) * 8;
                uint32_t r0, r1, r2, r3;
                ldsm_x4_t(r0, r1, r2, r3, smem_u32(&Bs[kk][nn]));
                b[pr * 2][0] = r0; b[pr * 2][1] = r1;
                b[pr * 2 + 1][0] = r2; b[pr * 2 + 1][1] = r3;
            }
            #pragma unroll
            for (int mt = 0; mt < 2; mt++)
                #pragma unroll
                for (int nt = 0; nt < 4; nt++)
                    mma_bf16(acc[mt][nt], a[mt], b[nt]);
        }
        __syncthreads();
    }
    // epilogue: bf16 output
    #pragma unroll
    for (int mt = 0; mt < 2; mt++) {
        int r_lo = row0 + wm + mt * 16 + (lane >> 2);
        #pragma unroll
        for (int nt = 0; nt < 4; nt++) {
            int c = col0 + wn + nt * 8 + (lane & 3) * 2;
            float v0 = acc[mt][nt][0], v1 = acc[mt][nt][1];
            float v2 = acc[mt][nt][2], v3 = acc[mt][nt][3];
            if (EPI) {
                float b0 = bias[c], b1 = bias[c + 1];
                v0 = fmaxf(v0 + b0, 0.f); v1 = fmaxf(v1 + b1, 0.f);
                v2 = fmaxf(v2 + b0, 0.f); v3 = fmaxf(v3 + b1, 0.f);
            }
            if (r_lo < M)
                *(__nv_bfloat162*)&C[(size_t)r_lo * N + c] = __floats2bfloat162_rn(v0, v1);
            if (r_lo + 8 < M)
                *(__nv_bfloat162*)&C[(size_t)(r_lo + 8) * N + c] = __floats2bfloat162_rn(v2, v3);
        }
    }
}

// ---------------- 64-dim normalized aggregation, bf16 in/out, fp32 accum ----------------
// one 8-lane group per node; each lane owns 8 consecutive bf16 (16B)
template<bool RELU>
__global__ void agg64_bf16_kernel(const uint4* __restrict__ in, uint4* __restrict__ out,
                                  const float* __restrict__ bias, int n) {
    int g = blockIdx.x * blockDim.x + threadIdx.x;
    int node = g >> 3;
    int sub  = g & 7;
    if (node >= n) return;
    float di = g_dinv[node];
    float w0 = di * di;
    float acc[8];
    {
        uint4 v = in[(size_t)node * 8 + sub];
        const uint32_t* p = (const uint32_t*)&v;
        #pragma unroll
        for (int q = 0; q < 4; q++) {
            float2 f = __bfloat1622float2(*(const __nv_bfloat162*)&p[q]);
            acc[q * 2]     = f.x * w0;
            acc[q * 2 + 1] = f.y * w0;
        }
    }
    int s0 = g_rowstart[node], s1 = g_rowstart[node + 1];
    for (int j = s0; j < s1; j++) {
        int s = __ldg(&g_csr[j]);
        float wgt = g_dinv[s] * di;
        uint4 v = in[(size_t)s * 8 + sub];
        const uint32_t* p = (const uint32_t*)&v;
        #pragma unroll
        for (int q = 0; q < 4; q++) {
            float2 f = __bfloat1622float2(*(const __nv_bfloat162*)&p[q]);
            acc[q * 2]     = fmaf(wgt, f.x, acc[q * 2]);
            acc[q * 2 + 1] = fmaf(wgt, f.y, acc[q * 2 + 1]);
        }
    }
    if (RELU) {
        #pragma unroll
        for (int q = 0; q < 8; q++)
            acc[q] = fmaxf(acc[q] + bias[sub * 8 + q], 0.0f);
    }
    uint4 o;
    uint32_t* po = (uint32_t*)&o;
    #pragma unroll
    for (int q = 0; q < 4; q++)
        *(__nv_bfloat162*)&po[q] = __floats2bfloat162_rn(acc[q * 2], acc[q * 2 + 1]);
    out[(size_t)node * 8 + sub] = o;
}

// ---------------- layer 3: row dot (bf16 h2) + self term ----------------
__global__ void rowdot_z_kernel(const __nv_bfloat16* __restrict__ h2,
                                const float* __restrict__ W3, int n) {
    int t = blockIdx.x * blockDim.x + threadIdx.x;
    int node = t >> 5;
    int lane = t & 31;
    if (node >= n) return;
    uint4 v = *(const uint4*)&h2[(size_t)node * D2 + lane * 8];
    const uint32_t* p = (const uint32_t*)&v;
    const float* wp = &W3[lane * 8];
    float s = 0.0f;
    #pragma unroll
    for (int q = 0; q < 4; q++) {
        float2 f = __bfloat1622float2(*(const __nv_bfloat162*)&p[q]);
        s = fmaf(f.x, wp[q * 2], s);
        s = fmaf(f.y, wp[q * 2 + 1], s);
    }
    #pragma unroll
    for (int o = 16; o; o >>= 1) s += __shfl_xor_sync(0xffffffffu, s, o);
    if (lane == 0) {
        g_xw3[node] = s;
        float di = g_dinv[node];
        g_z[node] = di * di * s;
    }
}

// ---------------- scalar aggregation + fused BCE loss ----------------
__global__ void aggz_loss_kernel(const float* __restrict__ y, const float* __restrict__ b3,
                                 float* __restrict__ out, int n) {
    int i = blockIdx.x * blockDim.x + threadIdx.x;
    float l = 0.0f;
    if (i < n) {
        float di = g_dinv[i];
        float acc = g_z[i];
        for (int j = g_rowstart[i]; j < g_rowstart[i + 1]; j++) {
            int s = g_csr[j];
            acc = fmaf(g_dinv[s] * di, g_xw3[s], acc);
        }
        float z = acc + b3[0];
        float sp = fmaxf(z, 0.0f) + log1pf(expf(-fabsf(z)));
        l = sp - y[i] * z;
    }
    __shared__ float red[256];
    red[threadIdx.x] = l;
    __syncthreads();
    #pragma unroll
    for (int o = 128; o; o >>= 1) {
        if (threadIdx.x < o) red[threadIdx.x] += red[threadIdx.x + o];
        __syncthreads();
    }
    if (threadIdx.x == 0) atomicAdd(out, red[0] * (1.0f / (float)n));
}

// ---------------- launch ----------------
extern "C" void kernel_launch(void* const* d_in, const int* in_sizes, int n_in,
                              void* d_out, int out_size) {
    const float* x   = (const float*)d_in[0];
    const int*   ei  = (const int*)d_in[1];
    const float* y   = (const float*)d_in[2];
    const float* W1  = (const float*)d_in[3];
    const float* b1  = (const float*)d_in[4];
    const float* W2  = (const float*)d_in[5];
    const float* b2  = (const float*)d_in[6];
    const float* W3  = (const float*)d_in[7];
    const float* b3  = (const float*)d_in[8];
    float* out = (float*)d_out;

    int n = in_sizes[0] / F0;      // 100000
    int e = in_sizes[1] / 2;       // 1600000
    const int* src = ei;
    const int* dst = ei + e;

    void *p_xw1, *p_h1, *p_a2, *p_h2;
    cudaGetSymbolAddress(&p_xw1, g_xw1);
    cudaGetSymbolAddress(&p_h1,  g_h1);
    cudaGetSymbolAddress(&p_a2,  g_a2);
    cudaGetSymbolAddress(&p_h2,  g_h2);

    static cudaStream_t s2 = nullptr;
    static cudaEvent_t evA = nullptr, evB = nullptr;
    if (!s2) {
        cudaStreamCreateWithFlags(&s2, cudaStreamNonBlocking);
        cudaEventCreateWithFlags(&evA, cudaEventDisableTiming);
        cudaEventCreateWithFlags(&evB, cudaEventDisableTiming);
    }

    int nb = (n + 255) / 256;

    // fork: gemm1 (x @ W1, independent of graph structure) on s2
    cudaEventRecord(evA, 0);
    cudaStreamWaitEvent(s2, evA, 0);
    gemm_tc_kernel<float, false><<<dim3(1, (n + 127) / 128), 256, 0, s2>>>(
        x, W1, nullptr, (__nv_bfloat16*)p_xw1, n, D1, F0);
    cudaEventRecord(evB, s2);

    // stream 0: graph structure build
    init_kernel<<<nb, 256>>>(out, n);
    hist_kernel<<<(e + 255) / 256, 256>>>(dst, e);
    bsumdinv_kernel<<<nb, 256>>>(n);
    bscan_kernel<<<1, 512>>>(nb, n);
    rowstart_kernel<<<nb, 256>>>(n);
    fill_kernel<<<(e + 255) / 256, 256>>>(src, dst, e);

    // join
    cudaStreamWaitEvent(0, evB, 0);

    // layer 1 aggregation (fused bias + relu), bf16
    agg64_bf16_kernel<true><<<(n * 8 + 255) / 256, 256>>>(
        (const uint4*)p_xw1, (uint4*)p_h1, b1, n);

    // layer 2: aggregate first (64-dim), then GEMM 64->256 with fused bias+relu
    agg64_bf16_kernel<false><<<(n * 8 + 255) / 256, 256>>>(
        (const uint4*)p_h1, (uint4*)p_a2, nullptr, n);
    gemm_tc_kernel<__nv_bfloat16, true><<<dim3(4, (n + 127) / 128), 256>>>(
        (const __nv_bfloat16*)p_a2, W2, b2, (__nv_bfloat16*)p_h2, n, D2, D1);

    // layer 3: row dot (256->1), scalar aggregation fused with BCE loss
    rowdot_z_kernel<<<(n * 32 + 255) / 256, 256>>>((const __nv_bfloat16*)p_h2, W3, n);
    aggz_loss_kernel<<<(n + 255) / 256, 256>>>(y, b3, out, n);
}

// round 5
// speedup vs baseline: 4.5474x; 1.1615x over previous
#include <cuda_runtime.h>
#include <cuda_bf16.h>
#include <math.h>
#include <stdint.h>

// ---------------- static problem sizes ----------------
#define NN  100000
#define EE  1600000
#define F0  512
#define D1  64
#define D2  256

// ---------------- device scratch ----------------
__device__ float g_dinv[NN];
__device__ int   g_cnt[NN];
__device__ int   g_rowstart[NN + 1];
__device__ int   g_cursor[NN];
__device__ int   g_csr[EE];
__device__ int   g_bsum[512];
__device__ __nv_bfloat16 g_xw1[(size_t)NN * D1];
__device__ __nv_bfloat16 g_h1 [(size_t)NN * D1];
__device__ float g_xw3[NN];

// ---------------- init: zero counters + xw3 + output ----------------
__global__ void init_kernel(float* out, int n) {
    int i = blockIdx.x * blockDim.x + threadIdx.x;
    if (i < n) { g_cnt[i] = 0; g_xw3[i] = 0.0f; }
    if (i == 0) out[0] = 0.0f;
}

__global__ void hist_kernel(const int* __restrict__ dst, int e) {
    int i = blockIdx.x * blockDim.x + threadIdx.x;
    if (i < e) atomicAdd(&g_cnt[dst[i]], 1);
}

// ---------------- dinv + per-block sums (fused) ----------------
__global__ void bsumdinv_kernel(int n) {
    __shared__ int wsum[8];
    int i = blockIdx.x * 256 + threadIdx.x;
    int v = (i < n) ? g_cnt[i] : 0;
    if (i < n) g_dinv[i] = rsqrtf((float)(v + 1));
    int s = v;
    #pragma unroll
    for (int o = 16; o; o >>= 1) s += __shfl_xor_sync(0xffffffffu, s, o);
    if ((threadIdx.x & 31) == 0) wsum[threadIdx.x >> 5] = s;
    __syncthreads();
    if (threadIdx.x == 0) {
        int t = 0;
        #pragma unroll
        for (int w = 0; w < 8; w++) t += wsum[w];
        g_bsum[blockIdx.x] = t;
    }
}

__global__ void bscan_kernel(int nb, int n) {
    __shared__ int s[512];
    int t = threadIdx.x;
    int orig = (t < nb) ? g_bsum[t] : 0;
    s[t] = orig;
    __syncthreads();
    #pragma unroll
    for (int o = 1; o < 512; o <<= 1) {
        int v = (t >= o) ? s[t - o] : 0;
        __syncthreads();
        s[t] += v;
        __syncthreads();
    }
    if (t < nb) g_bsum[t] = s[t] - orig;
    if (t == 0) g_rowstart[n] = s[511];
}

__global__ void rowstart_kernel(int n) {
    __shared__ int warp_off[8];
    int tid = threadIdx.x;
    int i = blockIdx.x * 256 + tid;
    int v = (i < n) ? g_cnt[i] : 0;
    int x = v;
    #pragma unroll
    for (int o = 1; o < 32; o <<= 1) {
        int t = __shfl_up_sync(0xffffffffu, x, o);
        if ((tid & 31) >= o) x += t;
    }
    if ((tid & 31) == 31) warp_off[tid >> 5] = x;
    __syncthreads();
    if (tid < 8) {
        int w = warp_off[tid];
        int y = w;
        #pragma unroll
        for (int o = 1; o < 8; o <<= 1) {
            int t = __shfl_up_sync(0xffu, y, o);
            if (tid >= o) y += t;
        }
        warp_off[tid] = y - w;
    }
    __syncthreads();
    if (i < n) {
        int rs = g_bsum[blockIdx.x] + x - v + warp_off[tid >> 5];
        g_rowstart[i] = rs;
        g_cursor[i] = rs;
    }
}

__global__ void fill_kernel(const int* __restrict__ src, const int* __restrict__ dst, int e) {
    int i = blockIdx.x * blockDim.x + threadIdx.x;
    if (i < e) {
        int p = atomicAdd(&g_cursor[dst[i]], 1);
        g_csr[p] = src[i];
    }
}

// ---------------- tensor-core helpers ----------------
__device__ __forceinline__ uint32_t smem_u32(const void* p) {
    return (uint32_t)__cvta_generic_to_shared(p);
}
__device__ __forceinline__ void ldsm_x4(uint32_t& r0, uint32_t& r1, uint32_t& r2, uint32_t& r3, uint32_t a) {
    asm volatile("ldmatrix.sync.aligned.m8n8.x4.shared.b16 {%0,%1,%2,%3}, [%4];\n"
                 : "=r"(r0), "=r"(r1), "=r"(r2), "=r"(r3) : "r"(a));
}
__device__ __forceinline__ void ldsm_x4_t(uint32_t& r0, uint32_t& r1, uint32_t& r2, uint32_t& r3, uint32_t a) {
    asm volatile("ldmatrix.sync.aligned.m8n8.x4.trans.shared.b16 {%0,%1,%2,%3}, [%4];\n"
                 : "=r"(r0), "=r"(r1), "=r"(r2), "=r"(r3) : "r"(a));
}
__device__ __forceinline__ void mma_bf16(float* c, const uint32_t* a, const uint32_t* b) {
    asm volatile(
        "mma.sync.aligned.m16n8k16.row.col.f32.bf16.bf16.f32 "
        "{%0,%1,%2,%3}, {%4,%5,%6,%7}, {%8,%9}, {%0,%1,%2,%3};\n"
        : "+f"(c[0]), "+f"(c[1]), "+f"(c[2]), "+f"(c[3])
        : "r"(a[0]), "r"(a[1]), "r"(a[2]), "r"(a[3]), "r"(b[0]), "r"(b[1]));
}

// ---------------- gemm1: xw1 = x @ W1 (fp32 in, bf16 out), double-buffered smem ----
// BM=128, BN=64(=D1), BK=64, K=512. 8 warps: 4 x M, 2 x N, 32x32 warp tiles.
__global__ void __launch_bounds__(256)
gemm1_kernel(const float* __restrict__ A, const float* __restrict__ B, int M) {
    __shared__ __align__(16) __nv_bfloat16 As[2][128][72];
    __shared__ __align__(16) __nv_bfloat16 Bs[2][64][72];
    const int tid = threadIdx.x, lane = tid & 31, w = tid >> 5;
    const int wm = (w & 3) * 32, wn = (w >> 2) * 32;
    const int row0 = blockIdx.y * 128;

    float acc[2][4][4];
    #pragma unroll
    for (int mt = 0; mt < 2; mt++)
        #pragma unroll
        for (int nt = 0; nt < 4; nt++)
            #pragma unroll
            for (int r = 0; r < 4; r++) acc[mt][nt][r] = 0.0f;

    float4 a_f[8], b_f[4];
    auto load_regs = [&](int k0) {
        #pragma unroll
        for (int i = 0; i < 8; i++) {
            int idx = tid + i * 256;
            int r = idx >> 4, cq = idx & 15;
            int gr = row0 + r;
            a_f[i] = (gr < M) ? *(const float4*)&A[(size_t)gr * F0 + k0 + cq * 4]
                              : make_float4(0.f, 0.f, 0.f, 0.f);
        }
        #pragma unroll
        for (int i = 0; i < 4; i++) {
            int idx = tid + i * 256;
            int r = idx >> 4, cq = idx & 15;
            b_f[i] = *(const float4*)&B[(size_t)(k0 + r) * D1 + cq * 4];
        }
    };
    auto store_smem = [&](int buf) {
        #pragma unroll
        for (int i = 0; i < 8; i++) {
            int idx = tid + i * 256;
            int r = idx >> 4, cq = idx & 15;
            *(__nv_bfloat162*)&As[buf][r][cq * 4]     = __floats2bfloat162_rn(a_f[i].x, a_f[i].y);
            *(__nv_bfloat162*)&As[buf][r][cq * 4 + 2] = __floats2bfloat162_rn(a_f[i].z, a_f[i].w);
        }
        #pragma unroll
        for (int i = 0; i < 4; i++) {
            int idx = tid + i * 256;
            int r = idx >> 4, cq = idx & 15;
            *(__nv_bfloat162*)&Bs[buf][r][cq * 4]     = __floats2bfloat162_rn(b_f[i].x, b_f[i].y);
            *(__nv_bfloat162*)&Bs[buf][r][cq * 4 + 2] = __floats2bfloat162_rn(b_f[i].z, b_f[i].w);
        }
    };

    load_regs(0);
    store_smem(0);
    __syncthreads();
    int cur = 0;
    for (int k0 = 0; k0 < F0; k0 += 64) {
        bool more = (k0 + 64 < F0);
        if (more) load_regs(k0 + 64);
        #pragma unroll
        for (int ks = 0; ks < 4; ks++) {
            uint32_t a[2][4];
            #pragma unroll
            for (int mt = 0; mt < 2; mt++) {
                int rrow = wm + mt * 16 + (lane & 7) + ((lane >> 3) & 1) * 8;
                int ccol = ks * 16 + (lane >> 4) * 8;
                ldsm_x4(a[mt][0], a[mt][1], a[mt][2], a[mt][3], smem_u32(&As[cur][rrow][ccol]));
            }
            uint32_t b[4][2];
            #pragma unroll
            for (int pr = 0; pr < 2; pr++) {
                int kk = ks * 16 + ((lane >> 3) & 1) * 8 + (lane & 7);
                int nn = wn + pr * 16 + (lane >> 4) * 8;
                uint32_t r0, r1, r2, r3;
                ldsm_x4_t(r0, r1, r2, r3, smem_u32(&Bs[cur][kk][nn]));
                b[pr * 2][0] = r0; b[pr * 2][1] = r1;
                b[pr * 2 + 1][0] = r2; b[pr * 2 + 1][1] = r3;
            }
            #pragma unroll
            for (int mt = 0; mt < 2; mt++)
                #pragma unroll
                for (int nt = 0; nt < 4; nt++)
                    mma_bf16(acc[mt][nt], a[mt], b[nt]);
        }
        if (more) store_smem(cur ^ 1);
        __syncthreads();
        cur ^= 1;
    }
    #pragma unroll
    for (int mt = 0; mt < 2; mt++) {
        int r_lo = row0 + wm + mt * 16 + (lane >> 2);
        #pragma unroll
        for (int nt = 0; nt < 4; nt++) {
            int c = wn + nt * 8 + (lane & 3) * 2;
            if (r_lo < M)
                *(__nv_bfloat162*)&g_xw1[(size_t)r_lo * D1 + c] =
                    __floats2bfloat162_rn(acc[mt][nt][0], acc[mt][nt][1]);
            if (r_lo + 8 < M)
                *(__nv_bfloat162*)&g_xw1[(size_t)(r_lo + 8) * D1 + c] =
                    __floats2bfloat162_rn(acc[mt][nt][2], acc[mt][nt][3]);
        }
    }
}

// ---------------- layer 1 aggregation: h1 = relu(agg(xw1) + b1), bf16 ----------------
__global__ void agg1_kernel(const float* __restrict__ bias, int n) {
    int g = blockIdx.x * blockDim.x + threadIdx.x;
    int node = g >> 3;
    int sub  = g & 7;
    if (node >= n) return;
    const uint4* in = (const uint4*)g_xw1;
    float di = g_dinv[node];
    float w0 = di * di;
    float acc[8];
    {
        uint4 v = in[(size_t)node * 8 + sub];
        const uint32_t* p = (const uint32_t*)&v;
        #pragma unroll
        for (int q = 0; q < 4; q++) {
            float2 f = __bfloat1622float2(*(const __nv_bfloat162*)&p[q]);
            acc[q * 2]     = f.x * w0;
            acc[q * 2 + 1] = f.y * w0;
        }
    }
    int s0 = g_rowstart[node], s1 = g_rowstart[node + 1];
    for (int j = s0; j < s1; j++) {
        int s = __ldg(&g_csr[j]);
        float wgt = g_dinv[s] * di;
        uint4 v = in[(size_t)s * 8 + sub];
        const uint32_t* p = (const uint32_t*)&v;
        #pragma unroll
        for (int q = 0; q < 4; q++) {
            float2 f = __bfloat1622float2(*(const __nv_bfloat162*)&p[q]);
            acc[q * 2]     = fmaf(wgt, f.x, acc[q * 2]);
            acc[q * 2 + 1] = fmaf(wgt, f.y, acc[q * 2 + 1]);
        }
    }
    uint4 o;
    uint32_t* po = (uint32_t*)&o;
    #pragma unroll
    for (int q = 0; q < 4; q++) {
        float v0 = fmaxf(acc[q * 2]     + bias[sub * 8 + q * 2],     0.0f);
        float v1 = fmaxf(acc[q * 2 + 1] + bias[sub * 8 + q * 2 + 1], 0.0f);
        *(__nv_bfloat162*)&po[q] = __floats2bfloat162_rn(v0, v1);
    }
    ((uint4*)g_h1)[(size_t)node * 8 + sub] = o;
}

// ---------------- fused layer 2+3: agg(h1) -> @W2+b2, relu, dot W3 -> xw3 --------
// One block = 128 nodes. Prologue aggregates into smem; A frags hoisted;
// loop 4 column-chunks of W2; epilogue accumulates partial W3 dots in regs.
__global__ void __launch_bounds__(256)
fused_l2_kernel(const float* __restrict__ W2, const float* __restrict__ b2,
                const float* __restrict__ W3, int n) {
    __shared__ __align__(16) __nv_bfloat16 As[128][72];
    __shared__ __align__(16) __nv_bfloat16 Bs[64][72];
    const int tid = threadIdx.x, lane = tid & 31, w = tid >> 5;
    const int wm = (w & 3) * 32, wn = (w >> 2) * 32;
    const int row0 = blockIdx.x * 128;

    // ---- prologue: aggregate 128 rows of h1 into As (fp32 accum -> bf16) ----
    const uint4* in = (const uint4*)g_h1;
    #pragma unroll
    for (int it = 0; it < 4; it++) {
        int r = (tid >> 3) + it * 32;
        int sub = tid & 7;
        int node = row0 + r;
        float acc[8];
        #pragma unroll
        for (int q = 0; q < 8; q++) acc[q] = 0.0f;
        if (node < n) {
            float di = g_dinv[node];
            float w0 = di * di;
            uint4 v = in[(size_t)node * 8 + sub];
            const uint32_t* p = (const uint32_t*)&v;
            #pragma unroll
            for (int q = 0; q < 4; q++) {
                float2 f = __bfloat1622float2(*(const __nv_bfloat162*)&p[q]);
                acc[q * 2]     = f.x * w0;
                acc[q * 2 + 1] = f.y * w0;
            }
            int s0 = g_rowstart[node], s1 = g_rowstart[node + 1];
            for (int j = s0; j < s1; j++) {
                int s = __ldg(&g_csr[j]);
                float wgt = g_dinv[s] * di;
                uint4 vv = in[(size_t)s * 8 + sub];
                const uint32_t* pp = (const uint32_t*)&vv;
                #pragma unroll
                for (int q = 0; q < 4; q++) {
                    float2 f = __bfloat1622float2(*(const __nv_bfloat162*)&pp[q]);
                    acc[q * 2]     = fmaf(wgt, f.x, acc[q * 2]);
                    acc[q * 2 + 1] = fmaf(wgt, f.y, acc[q * 2 + 1]);
                }
            }
        }
        uint4 o;
        uint32_t* po = (uint32_t*)&o;
        #pragma unroll
        for (int q = 0; q < 4; q++)
            *(__nv_bfloat162*)&po[q] = __floats2bfloat162_rn(acc[q * 2], acc[q * 2 + 1]);
        *(uint4*)&As[r][sub * 8] = o;
    }
    __syncthreads();

    // ---- hoist A fragments (constant across column chunks) ----
    uint32_t afrag[4][2][4];
    #pragma unroll
    for (int ks = 0; ks < 4; ks++) {
        #pragma unroll
        for (int mt = 0; mt < 2; mt++) {
            int rrow = wm + mt * 16 + (lane & 7) + ((lane >> 3) & 1) * 8;
            int ccol = ks * 16 + (lane >> 4) * 8;
            ldsm_x4(afrag[ks][mt][0], afrag[ks][mt][1], afrag[ks][mt][2], afrag[ks][mt][3],
                    smem_u32(&As[rrow][ccol]));
        }
    }

    float rs0[2], rs1[2];   // partial W3 dots: rows r_lo, r_lo+8 for mt=0,1
    rs0[0] = rs0[1] = rs1[0] = rs1[1] = 0.0f;

    for (int ch = 0; ch < 4; ch++) {
        int cols0 = ch * 64;
        // stage Bs = bf16(W2[0:64, cols0:cols0+64])
        #pragma unroll
        for (int i = 0; i < 4; i++) {
            int idx = tid + i * 256;
            int r = idx >> 4, cq = idx & 15;
            float4 v = *(const float4*)&W2[(size_t)r * D2 + cols0 + cq * 4];
            *(__nv_bfloat162*)&Bs[r][cq * 4]     = __floats2bfloat162_rn(v.x, v.y);
            *(__nv_bfloat162*)&Bs[r][cq * 4 + 2] = __floats2bfloat162_rn(v.z, v.w);
        }
        __syncthreads();

        float acc[2][4][4];
        #pragma unroll
        for (int mt = 0; mt < 2; mt++)
            #pragma unroll
            for (int nt = 0; nt < 4; nt++)
                #pragma unroll
                for (int r = 0; r < 4; r++) acc[mt][nt][r] = 0.0f;

        #pragma unroll
        for (int ks = 0; ks < 4; ks++) {
            uint32_t b[4][2];
            #pragma unroll
            for (int pr = 0; pr < 2; pr++) {
                int kk = ks * 16 + ((lane >> 3) & 1) * 8 + (lane & 7);
                int nn = wn + pr * 16 + (lane >> 4) * 8;
                uint32_t r0, r1, r2, r3;
                ldsm_x4_t(r0, r1, r2, r3, smem_u32(&Bs[kk][nn]));
                b[pr * 2][0] = r0; b[pr * 2][1] = r1;
                b[pr * 2 + 1][0] = r2; b[pr * 2 + 1][1] = r3;
            }
            #pragma unroll
            for (int mt = 0; mt < 2; mt++)
                #pragma unroll
                for (int nt = 0; nt < 4; nt++)
                    mma_bf16(acc[mt][nt], afrag[ks][mt], b[nt]);
        }
        // epilogue: bias + relu + partial dot with W3
        #pragma unroll
        for (int mt = 0; mt < 2; mt++) {
            #pragma unroll
            for (int nt = 0; nt < 4; nt++) {
                int c = cols0 + wn + nt * 8 + (lane & 3) * 2;
                float bb0 = b2[c], bb1 = b2[c + 1];
                float w30 = W3[c], w31 = W3[c + 1];
                float v0 = fmaxf(acc[mt][nt][0] + bb0, 0.f);
                float v1 = fmaxf(acc[mt][nt][1] + bb1, 0.f);
                float v2 = fmaxf(acc[mt][nt][2] + bb0, 0.f);
                float v3 = fmaxf(acc[mt][nt][3] + bb1, 0.f);
                rs0[mt] = fmaf(v0, w30, fmaf(v1, w31, rs0[mt]));
                rs1[mt] = fmaf(v2, w30, fmaf(v3, w31, rs1[mt]));
            }
        }
        __syncthreads();   // all warps done reading Bs before restage
    }

    // reduce partial dots across the 4 lanes sharing a row (lane&3)
    #pragma unroll
    for (int mt = 0; mt < 2; mt++) {
        #pragma unroll
        for (int o = 1; o < 4; o <<= 1) {
            rs0[mt] += __shfl_xor_sync(0xffffffffu, rs0[mt], o);
            rs1[mt] += __shfl_xor_sync(0xffffffffu, rs1[mt], o);
        }
    }
    if ((lane & 3) == 0) {
        #pragma unroll
        for (int mt = 0; mt < 2; mt++) {
            int r_lo = row0 + wm + mt * 16 + (lane >> 2);
            if (r_lo < n)     atomicAdd(&g_xw3[r_lo], rs0[mt]);
            if (r_lo + 8 < n) atomicAdd(&g_xw3[r_lo + 8], rs1[mt]);
        }
    }
}

// ---------------- scalar aggregation of xw3 + fused BCE loss ----------------
__global__ void aggz_loss_kernel(const float* __restrict__ y, const float* __restrict__ b3,
                                 float* __restrict__ out, int n) {
    int i = blockIdx.x * blockDim.x + threadIdx.x;
    float l = 0.0f;
    if (i < n) {
        float di = g_dinv[i];
        float acc = di * di * g_xw3[i];
        for (int j = g_rowstart[i]; j < g_rowstart[i + 1]; j++) {
            int s = g_csr[j];
            acc = fmaf(g_dinv[s] * di, g_xw3[s], acc);
        }
        float z = acc + b3[0];
        float sp = fmaxf(z, 0.0f) + log1pf(expf(-fabsf(z)));
        l = sp - y[i] * z;
    }
    __shared__ float red[256];
    red[threadIdx.x] = l;
    __syncthreads();
    #pragma unroll
    for (int o = 128; o; o >>= 1) {
        if (threadIdx.x < o) red[threadIdx.x] += red[threadIdx.x + o];
        __syncthreads();
    }
    if (threadIdx.x == 0) atomicAdd(out, red[0] * (1.0f / (float)n));
}

// ---------------- launch ----------------
extern "C" void kernel_launch(void* const* d_in, const int* in_sizes, int n_in,
                              void* d_out, int out_size) {
    const float* x   = (const float*)d_in[0];
    const int*   ei  = (const int*)d_in[1];
    const float* y   = (const float*)d_in[2];
    const float* W1  = (const float*)d_in[3];
    const float* b1  = (const float*)d_in[4];
    const float* W2  = (const float*)d_in[5];
    const float* b2  = (const float*)d_in[6];
    const float* W3  = (const float*)d_in[7];
    const float* b3  = (const float*)d_in[8];
    float* out = (float*)d_out;

    int n = in_sizes[0] / F0;      // 100000
    int e = in_sizes[1] / 2;       // 1600000
    const int* src = ei;
    const int* dst = ei + e;

    static cudaStream_t s2 = nullptr;
    static cudaEvent_t evA = nullptr, evB = nullptr;
    if (!s2) {
        cudaStreamCreateWithFlags(&s2, cudaStreamNonBlocking);
        cudaEventCreateWithFlags(&evA, cudaEventDisableTiming);
        cudaEventCreateWithFlags(&evB, cudaEventDisableTiming);
    }

    int nb = (n + 255) / 256;
    int nblk = (n + 127) / 128;    // 782

    // fork: gemm1 (x @ W1, independent of graph structure) on s2
    cudaEventRecord(evA, 0);
    cudaStreamWaitEvent(s2, evA, 0);
    gemm1_kernel<<<dim3(1, nblk), 256, 0, s2>>>(x, W1, n);
    cudaEventRecord(evB, s2);

    // stream 0: graph structure build
    init_kernel<<<nb, 256>>>(out, n);
    hist_kernel<<<(e + 255) / 256, 256>>>(dst, e);
    bsumdinv_kernel<<<nb, 256>>>(n);
    bscan_kernel<<<1, 512>>>(nb, n);
    rowstart_kernel<<<nb, 256>>>(n);
    fill_kernel<<<(e + 255) / 256, 256>>>(src, dst, e);

    // join
    cudaStreamWaitEvent(0, evB, 0);

    // layer 1 aggregation (fused bias + relu)
    agg1_kernel<<<(n * 8 + 255) / 256, 256>>>(b1, n);

    // fused layer 2 + 3 front: agg(h1) @ W2 + b2, relu, dot W3 -> g_xw3
    fused_l2_kernel<<<nblk, 256>>>(W2, b2, W3, n);

    // final: scalar aggregation + BCE loss
    aggz_loss_kernel<<<(n + 255) / 256, 256>>>(y, b3, out, n);
}